// round 1
// baseline (speedup 1.0000x reference)
#include <cuda_runtime.h>
#include <float.h>

// TropConv2D: out[b,ho,wo,f] = max_k(p_k + w_kf) - min_k(p_k + w_kf) + bias[f]
// p_k = x[b, ho+i, wo+j, c], k = (i*3+j)*32 + c
#define KH 3
#define KW 3
#define CH 32
#define NF 64
#define HH 32
#define WW 32
#define HO 30
#define WO 30
#define KK (KH*KW*CH)   // 288

#define XS_COLS 34                         // padded width (wo up to 31, +j up to 2)
#define W_S_FLOATS (KK*NF)                 // 18432
#define X_S_FLOATS (KH*XS_COLS*CH)         // 3264
#define SMEM_BYTES ((W_S_FLOATS + X_S_FLOATS)*4)  // 86784

#define UPD4(P, WV, MX, MN) do {                                   \
    float s_;                                                      \
    s_ = (P) + (WV).x; (MX).x = fmaxf((MX).x, s_); (MN).x = fminf((MN).x, s_); \
    s_ = (P) + (WV).y; (MX).y = fmaxf((MX).y, s_); (MN).y = fminf((MN).y, s_); \
    s_ = (P) + (WV).z; (MX).z = fmaxf((MX).z, s_); (MN).z = fminf((MN).z, s_); \
    s_ = (P) + (WV).w; (MX).w = fmaxf((MX).w, s_); (MN).w = fminf((MN).w, s_); \
  } while (0)

__global__ __launch_bounds__(256, 2)
void tropconv_kernel(const float* __restrict__ x,
                     const float* __restrict__ w,
                     const float* __restrict__ bias,
                     float* __restrict__ out)
{
    extern __shared__ float smem[];
    float* w_s = smem;                       // [KK][NF]
    float* x_s = smem + W_S_FLOATS;          // [KH][XS_COLS][CH]

    const int ho  = blockIdx.x;
    const int b   = blockIdx.y;
    const int tid = threadIdx.x;

    // ---- load w (18432 floats = 4608 float4; 18 per thread) ----
    {
        const float4* wg  = (const float4*)w;
        float4*       ws4 = (float4*)w_s;
        #pragma unroll
        for (int i = 0; i < 18; i++)
            ws4[tid + 256 * i] = wg[tid + 256 * i];
    }
    // ---- load x rows ho..ho+2 into padded x_s ----
    {
        // 3*32*32 floats = 768 float4
        for (int v = tid; v < KH * WW * (CH/4); v += 256) {
            int i   = v / (WW * (CH/4));
            int rem = v % (WW * (CH/4));
            int col = rem / (CH/4);
            int c4  = rem % (CH/4);
            float4 val = *(const float4*)(x + (((size_t)(b*HH + ho + i)*WW + col)*CH) + c4*4);
            *(float4*)(x_s + ((i*XS_COLS + col)*CH) + c4*4) = val;
        }
        // zero the 2 padded columns (results using them are discarded, but keep
        // the values finite/deterministic)
        for (int v = tid; v < KH * 2 * CH; v += 256) {
            int i   = v / (2*CH);
            int rem = v % (2*CH);
            int col = WW + rem / CH;
            int c   = rem % CH;
            x_s[(i*XS_COLS + col)*CH + c] = 0.f;
        }
    }
    __syncthreads();

    // thread = (pp, fg): 2 positions (wo0, wo0+16) x 4 filters
    const int fg  = tid & 15;
    const int pp  = tid >> 4;       // 0..15
    const int f0  = fg * 4;
    const int wo0 = pp;
    const int wo1 = pp + 16;

    float4 mx0 = make_float4(-FLT_MAX,-FLT_MAX,-FLT_MAX,-FLT_MAX);
    float4 mn0 = make_float4( FLT_MAX, FLT_MAX, FLT_MAX, FLT_MAX);
    float4 mx1 = mx0, mn1 = mn0;

    #pragma unroll 1
    for (int ij = 0; ij < KH*KW; ij++) {
        const int i = ij / 3;
        const int j = ij - i * 3;
        const float* pr0 = x_s + (i*XS_COLS + wo0 + j) * CH;
        const float* pr1 = x_s + (i*XS_COLS + wo1 + j) * CH;
        const float* wr  = w_s + (ij*CH) * NF + f0;
        #pragma unroll
        for (int c = 0; c < CH; c += 4) {
            float4 p0 = *(const float4*)(pr0 + c);
            float4 p1 = *(const float4*)(pr1 + c);
            float4 w0 = *(const float4*)(wr + (c+0)*NF);
            float4 w1 = *(const float4*)(wr + (c+1)*NF);
            float4 w2 = *(const float4*)(wr + (c+2)*NF);
            float4 w3 = *(const float4*)(wr + (c+3)*NF);
            UPD4(p0.x, w0, mx0, mn0);
            UPD4(p0.y, w1, mx0, mn0);
            UPD4(p0.z, w2, mx0, mn0);
            UPD4(p0.w, w3, mx0, mn0);
            UPD4(p1.x, w0, mx1, mn1);
            UPD4(p1.y, w1, mx1, mn1);
            UPD4(p1.z, w2, mx1, mn1);
            UPD4(p1.w, w3, mx1, mn1);
        }
    }

    const float4 bi = *(const float4*)(bias + f0);

    {
        float4 r;
        r.x = mx0.x - mn0.x + bi.x;
        r.y = mx0.y - mn0.y + bi.y;
        r.z = mx0.z - mn0.z + bi.z;
        r.w = mx0.w - mn0.w + bi.w;
        size_t o = (((size_t)(b*HO + ho)*WO + wo0)*NF + f0);
        *(float4*)(out + o) = r;
    }
    if (wo1 < WO) {
        float4 r;
        r.x = mx1.x - mn1.x + bi.x;
        r.y = mx1.y - mn1.y + bi.y;
        r.z = mx1.z - mn1.z + bi.z;
        r.w = mx1.w - mn1.w + bi.w;
        size_t o = (((size_t)(b*HO + ho)*WO + wo1)*NF + f0);
        *(float4*)(out + o) = r;
    }
}

extern "C" void kernel_launch(void* const* d_in, const int* in_sizes, int n_in,
                              void* d_out, int out_size)
{
    const float* x    = (const float*)d_in[0];
    const float* w    = (const float*)d_in[1];
    const float* bias = (const float*)d_in[2];
    float*       out  = (float*)d_out;

    const int B = in_sizes[0] / (HH * WW * CH);   // = 8

    cudaFuncSetAttribute(tropconv_kernel,
                         cudaFuncAttributeMaxDynamicSharedMemorySize, SMEM_BYTES);
    dim3 grid(HO, B);
    tropconv_kernel<<<grid, 256, SMEM_BYTES>>>(x, w, bias, out);
}